// round 13
// baseline (speedup 1.0000x reference)
#include <cuda_runtime.h>
#include <cuda_fp16.h>
#include <cstdint>
#include <cstddef>

#define CB 4
#define CT 1024
#define CD 1024
#define CH 16
#define CHS 64
#define CL 4
#define CFF 4096
#define CV 32000
#define CQKV 3072

// ---------------- scratch (static __device__ arrays; no runtime alloc) ------
__device__ float g_x  [(size_t)CB*CT*CD];
__device__ float g_h  [(size_t)CB*CT*CD];
__device__ float g_qkv[(size_t)CB*CT*CQKV];   // q | k | v concat along cols
__device__ float g_o  [(size_t)CB*CT*CD];
__device__ float g_ffn[(size_t)CB*CT*CFF];
__device__ float g_s  [(size_t)CB*CH*CT*CT];
__device__ float g_wt [(size_t)CD*CQKV];      // (D, 3*H*HS) qkv weights

// ---------------- helpers -----------------------------------------------------
__device__ __forceinline__ uint32_t f2h2(float lo, float hi) {
    uint32_t u;
    asm("cvt.rn.f16x2.f32 %0, %1, %2;" : "=r"(u) : "f"(hi), "f"(lo));
    return u;
}
__device__ __forceinline__ void sts128(uint32_t a, uint32_t u0, uint32_t u1,
                                       uint32_t u2, uint32_t u3) {
    asm volatile("st.shared.v4.b32 [%0], {%1,%2,%3,%4};"
                 :: "r"(a), "r"(u0), "r"(u1), "r"(u2), "r"(u3));
}
__device__ __forceinline__ uint32_t smem_u32(const void* p) {
    uint32_t a;
    asm("{ .reg .u64 t; cvta.to.shared.u64 t, %1; cvt.u32.u64 %0, t; }"
        : "=r"(a) : "l"(p));
    return a;
}
__device__ __forceinline__ void mma_f16(float* c,
    uint32_t a0, uint32_t a1, uint32_t a2, uint32_t a3,
    uint32_t b0, uint32_t b1)
{
    asm volatile(
        "mma.sync.aligned.m16n8k16.row.col.f32.f16.f16.f32 "
        "{%0,%1,%2,%3}, {%4,%5,%6,%7}, {%8,%9}, {%0,%1,%2,%3};"
        : "+f"(c[0]), "+f"(c[1]), "+f"(c[2]), "+f"(c[3])
        : "r"(a0), "r"(a1), "r"(a2), "r"(a3), "r"(b0), "r"(b1));
}

// ================= fp16 tensor-core GEMM ======================================
// C[M,N] = A[M,K] @ op(B) (+bias) (+res) (relu), fp32 in/out, fp16 compute.
// NTB=0: B gmem [K,N] row-major.  NTB=1: B gmem [N,K] row-major (C = A B^T).
// CMODE: 0 none; 1 causal tile-skip (scores); 2 causal K-limit (AV).
// Block tile 128x128, K-chunk 32. Requires M%128==0, K%32==0; N guarded.
// grid: x = M/128 (fast), y = ceil(N/128), z = batch.
// Batch: X += (z/hdiv)*sXo + (z%hdiv)*sXi.
template<int NTB, int CMODE>
__global__ __launch_bounds__(256, 2) void hgemm(
    const float* __restrict__ A, int lda, long long sAo, long long sAi,
    const float* __restrict__ B, int ldb, long long sBo, long long sBi,
    float* __restrict__ C, int ldc, long long sCo, long long sCi,
    int hdiv, int N, int K,
    const float* __restrict__ bias, const float* __restrict__ res, int relu)
{
    const int m0 = blockIdx.x * 128, n0 = blockIdx.y * 128;
    if (CMODE == 1 && n0 > m0 + 127) return;

    long long z = blockIdx.z, zo = z / hdiv, zi = z % hdiv;
    A += zo * sAo + zi * sAi;
    B += zo * sBo + zi * sBi;
    C += zo * sCo + zi * sCi;
    const float* resp = res ? (res + zo * sCo + zi * sCi) : nullptr;

    // smem: 128 rows x 16 half2 (K=32 halves), stride 20 half2 (conflict-free)
    __shared__ uint32_t As[128 * 20];
    __shared__ uint32_t Bs[128 * 20];
    const uint32_t aBase = smem_u32(As), bBase = smem_u32(Bs);

    const int tid  = threadIdx.x;
    const int lane = tid & 31, wid = tid >> 5;
    const int wm = wid & 1, wn = wid >> 1;      // 2 x 4 warp grid
    const int g = lane >> 2, q = lane & 3;

    // -------- producer indices --------
    const int ar = tid >> 1;                    // 0..127 (row)
    const int kb = (tid & 1) * 16;              // float k offset within chunk
    const int ks = (tid & 1) * 8;               // half2 col offset
    const float* Ap = A + (size_t)(m0 + ar) * lda + kb;

    const float* Bp;
    int nn = 0, kb2 = 0, bok = 1;
    if (NTB) {
        Bp = B + (size_t)(n0 + ar) * ldb + kb;
        bok = (n0 + ar) < N;
    } else {
        nn  = tid & 127;
        kb2 = (tid >> 7) * 16;
        Bp  = B + (size_t)kb2 * ldb + n0 + nn;
        bok = (n0 + nn) < N;
    }

    int KL = K;
    if (CMODE == 2) { int kl = m0 + 128; if (kl < KL) KL = kl; }

    float acc[4][4][4];
    #pragma unroll
    for (int i = 0; i < 4; i++)
        #pragma unroll
        for (int j = 0; j < 4; j++)
            #pragma unroll
            for (int e = 0; e < 4; e++) acc[i][j][e] = 0.f;

    float4 ra[4], rbt[4];
    float  rbn[16];

    auto loadAB = [&]() {
        #pragma unroll
        for (int j = 0; j < 4; j++) ra[j] = *(const float4*)(Ap + 4 * j);
        if (NTB) {
            if (bok) {
                #pragma unroll
                for (int j = 0; j < 4; j++) rbt[j] = *(const float4*)(Bp + 4 * j);
            } else {
                #pragma unroll
                for (int j = 0; j < 4; j++) rbt[j] = make_float4(0.f, 0.f, 0.f, 0.f);
            }
        } else {
            #pragma unroll
            for (int j = 0; j < 16; j++)
                rbn[j] = bok ? Bp[(size_t)j * ldb] : 0.f;
        }
    };
    auto storeAB = [&]() {
        uint32_t h[8];
        #pragma unroll
        for (int j = 0; j < 4; j++) {
            h[2*j]   = f2h2(ra[j].x, ra[j].y);
            h[2*j+1] = f2h2(ra[j].z, ra[j].w);
        }
        uint32_t aoff = aBase + (uint32_t)(ar * 20 + ks) * 4;
        sts128(aoff,      h[0], h[1], h[2], h[3]);
        sts128(aoff + 16, h[4], h[5], h[6], h[7]);
        if (NTB) {
            #pragma unroll
            for (int j = 0; j < 4; j++) {
                h[2*j]   = f2h2(rbt[j].x, rbt[j].y);
                h[2*j+1] = f2h2(rbt[j].z, rbt[j].w);
            }
            uint32_t boff = bBase + (uint32_t)(ar * 20 + ks) * 4;
            sts128(boff,      h[0], h[1], h[2], h[3]);
            sts128(boff + 16, h[4], h[5], h[6], h[7]);
        } else {
            #pragma unroll
            for (int j = 0; j < 8; j++) h[j] = f2h2(rbn[2*j], rbn[2*j+1]);
            uint32_t boff = bBase + (uint32_t)(nn * 20 + (kb2 >> 1)) * 4;
            sts128(boff,      h[0], h[1], h[2], h[3]);
            sts128(boff + 16, h[4], h[5], h[6], h[7]);
        }
    };

    // prologue: chunk kk=0
    loadAB();
    storeAB();
    __syncthreads();

    for (int kk = 32;; kk += 32) {
        const bool more = kk < KL;
        if (more) {
            Ap += 32;
            if (NTB) Bp += 32;
            else     Bp += (size_t)32 * ldb;
            loadAB();
        }

        #pragma unroll
        for (int s = 0; s < 2; s++) {
            const int q0 = s * 8;
            uint32_t af[4][4], bf[4][2];
            #pragma unroll
            for (int mi = 0; mi < 4; mi++) {
                int base = (wm * 64 + mi * 16 + g) * 20 + q0 + q;
                af[mi][0] = As[base];
                af[mi][1] = As[base + 160];
                af[mi][2] = As[base + 4];
                af[mi][3] = As[base + 164];
            }
            #pragma unroll
            for (int ni = 0; ni < 4; ni++) {
                int base = (wn * 32 + ni * 8 + g) * 20 + q0 + q;
                bf[ni][0] = Bs[base];
                bf[ni][1] = Bs[base + 4];
            }
            #pragma unroll
            for (int mi = 0; mi < 4; mi++)
                #pragma unroll
                for (int ni = 0; ni < 4; ni++)
                    mma_f16(acc[mi][ni], af[mi][0], af[mi][1], af[mi][2], af[mi][3],
                            bf[ni][0], bf[ni][1]);
        }

        if (!more) break;
        __syncthreads();
        storeAB();
        __syncthreads();
    }

    // -------- epilogue --------
    #pragma unroll
    for (int mi = 0; mi < 4; mi++) {
        int r0 = m0 + wm * 64 + mi * 16 + g;
        #pragma unroll
        for (int ni = 0; ni < 4; ni++) {
            int c0 = n0 + wn * 32 + ni * 8 + (q << 1);
            if (c0 >= N) continue;
            float b0 = 0.f, b1 = 0.f;
            if (bias) { b0 = bias[c0]; b1 = bias[c0 + 1]; }
            float v0 = acc[mi][ni][0] + b0, v1 = acc[mi][ni][1] + b1;
            float v2 = acc[mi][ni][2] + b0, v3 = acc[mi][ni][3] + b1;
            size_t o0 = (size_t)r0 * ldc + c0;
            size_t o1 = (size_t)(r0 + 8) * ldc + c0;
            if (resp) {
                float2 x0 = *(const float2*)(resp + o0); v0 += x0.x; v1 += x0.y;
                float2 x1 = *(const float2*)(resp + o1); v2 += x1.x; v3 += x1.y;
            }
            if (relu) {
                v0 = fmaxf(v0, 0.f); v1 = fmaxf(v1, 0.f);
                v2 = fmaxf(v2, 0.f); v3 = fmaxf(v3, 0.f);
            }
            float2 s0; s0.x = v0; s0.y = v1;
            float2 s1; s1.x = v2; s1.y = v3;
            *(float2*)(C + o0) = s0;
            *(float2*)(C + o1) = s1;
        }
    }
}

// ---------------- embedding -------------------------------------------------
__global__ void embed_kernel(const int* __restrict__ ids,
                             const float* __restrict__ te,
                             const float* __restrict__ pe,
                             float* __restrict__ x)
{
    size_t i = (size_t)blockIdx.x * blockDim.x + threadIdx.x;
    if (i >= (size_t)CB*CT*CD) return;
    int d = (int)(i % CD);
    size_t bt = i / CD;
    int t = (int)(bt % CT);
    x[i] = te[(size_t)ids[bt]*CD + d] + pe[(size_t)t*CD + d];
}

// ---------------- layernorm --------------------------------------------------
__global__ void layernorm_kernel(const float* __restrict__ x, float* __restrict__ y,
                                 const float* __restrict__ g, const float* __restrict__ bb)
{
    int row = blockIdx.x;
    const float* xr = x + (size_t)row * CD;
    float* yr = y + (size_t)row * CD;
    float s = 0.f, s2 = 0.f;
    for (int i = threadIdx.x; i < CD; i += blockDim.x) {
        float u = xr[i]; s += u; s2 += u*u;
    }
    __shared__ float rs[32], rs2[32], stats[2];
    #pragma unroll
    for (int o = 16; o; o >>= 1) {
        s  += __shfl_xor_sync(0xffffffffu, s,  o);
        s2 += __shfl_xor_sync(0xffffffffu, s2, o);
    }
    int wid = threadIdx.x >> 5;
    if ((threadIdx.x & 31) == 0) { rs[wid] = s; rs2[wid] = s2; }
    __syncthreads();
    if (threadIdx.x == 0) {
        float ts = 0.f, ts2 = 0.f;
        int nw = blockDim.x >> 5;
        for (int i = 0; i < nw; i++) { ts += rs[i]; ts2 += rs2[i]; }
        float m = ts / (float)CD;
        float var = ts2 / (float)CD - m*m;
        stats[0] = m; stats[1] = rsqrtf(var + 1e-5f);
    }
    __syncthreads();
    float m = stats[0], r = stats[1];
    for (int i = threadIdx.x; i < CD; i += blockDim.x)
        yr[i] = (xr[i] - m) * r * g[i] + bb[i];
}

// ---- fused wq/wk/wv transpose: 3 x (H,D,HS) -> (D, 3*H*HS) ld=3072 ----------
__global__ void transpose_w3(const float* __restrict__ wq,
                             const float* __restrict__ wk,
                             const float* __restrict__ wv,
                             float* __restrict__ dst)
{
    int fid = blockIdx.x * blockDim.x + threadIdx.x;  // float4 index
    const int per = (CD * CD) >> 2;                    // 262144
    if (fid >= 3 * per) return;
    int w = fid / per, r = fid - w * per;
    int d = r >> 8, rem = r & 255, hh = rem >> 4, e4 = (rem & 15) << 2;
    const float* src = (w == 0) ? wq : ((w == 1) ? wk : wv);
    float4 v = *(const float4*)(src + ((size_t)hh * CD + d) * CHS + e4);
    *(float4*)(dst + (size_t)d * CQKV + w * CD + hh * CHS + e4) = v;
}

// ---------------- causal softmax; zeros only to next 128 boundary ------------
__global__ void softmax_causal(float* __restrict__ S)
{
    int row = blockIdx.x;          // (b*H+h)*T + t
    int t = row & (CT - 1);
    float* p = S + (size_t)row * CT;
    int n = t + 1;
    const float scale = 0.03125f;  // 1024^-0.5

    __shared__ float red[32];
    __shared__ float bval;

    float m = -1e30f;
    for (int j = threadIdx.x; j < n; j += blockDim.x) m = fmaxf(m, p[j] * scale);
    #pragma unroll
    for (int o = 16; o; o >>= 1) m = fmaxf(m, __shfl_xor_sync(0xffffffffu, m, o));
    int wid = threadIdx.x >> 5;
    if ((threadIdx.x & 31) == 0) red[wid] = m;
    __syncthreads();
    if (threadIdx.x == 0) {
        float mm = -1e30f; int nw = blockDim.x >> 5;
        for (int i = 0; i < nw; i++) mm = fmaxf(mm, red[i]);
        bval = mm;
    }
    __syncthreads();
    float bmax = bval;

    float s = 0.f;
    for (int j = threadIdx.x; j < n; j += blockDim.x) {
        float e = __expf(p[j] * scale - bmax);
        p[j] = e; s += e;
    }
    __syncthreads();
    #pragma unroll
    for (int o = 16; o; o >>= 1) s += __shfl_xor_sync(0xffffffffu, s, o);
    if ((threadIdx.x & 31) == 0) red[wid] = s;
    __syncthreads();
    if (threadIdx.x == 0) {
        float ss = 0.f; int nw = blockDim.x >> 5;
        for (int i = 0; i < nw; i++) ss += red[i];
        bval = ss;
    }
    __syncthreads();
    float inv = 1.f / bval;
    for (int j = threadIdx.x; j < n; j += blockDim.x) p[j] *= inv;
    int zend = ((t >> 7) + 1) << 7;    // AV reads k < m0+128 only
    for (int j = n + threadIdx.x; j < zend; j += blockDim.x) p[j] = 0.f;
}

// ---------------- host orchestration ----------------------------------------
extern "C" void kernel_launch(void* const* d_in, const int* in_sizes, int n_in,
                              void* d_out, int out_size)
{
    (void)in_sizes; (void)n_in; (void)out_size;
    const int*   ids  = (const int*)  d_in[0];
    const float* tok  = (const float*)d_in[1];
    const float* pos  = (const float*)d_in[2];
    const float* wq   = (const float*)d_in[3];
    const float* wk   = (const float*)d_in[4];
    const float* wv   = (const float*)d_in[5];
    const float* wprj = (const float*)d_in[6];
    const float* bprj = (const float*)d_in[7];
    const float* ln1g = (const float*)d_in[8];
    const float* ln1b = (const float*)d_in[9];
    const float* ln2g = (const float*)d_in[10];
    const float* ln2b = (const float*)d_in[11];
    const float* w1   = (const float*)d_in[12];
    const float* b1   = (const float*)d_in[13];
    const float* w2   = (const float*)d_in[14];
    const float* b2   = (const float*)d_in[15];
    const float* lnfg = (const float*)d_in[16];
    const float* lnfb = (const float*)d_in[17];
    const float* wout = (const float*)d_in[18];
    const float* bout = (const float*)d_in[19];
    float* out = (float*)d_out;

    float *x, *h, *qkv, *o, *ffn, *s, *wt;
    cudaGetSymbolAddress((void**)&x,   g_x);
    cudaGetSymbolAddress((void**)&h,   g_h);
    cudaGetSymbolAddress((void**)&qkv, g_qkv);
    cudaGetSymbolAddress((void**)&o,   g_o);
    cudaGetSymbolAddress((void**)&ffn, g_ffn);
    cudaGetSymbolAddress((void**)&s,   g_s);
    cudaGetSymbolAddress((void**)&wt,  g_wt);

    const int NT = CB * CT;                       // 4096 rows
    const long long TQ = (long long)CT * CQKV;    // qkv batch stride (per b)
    const long long TD = (long long)CT * CD;
    const long long TT = (long long)CT * CT;

    // 1. embedding
    {
        size_t tot = (size_t)CB * CT * CD;
        embed_kernel<<<(unsigned)((tot + 255) / 256), 256>>>(ids, tok, pos, x);
    }

    for (int l = 0; l < CL; l++) {
        const size_t wOff = (size_t)l * CD * CD;

        // 2. ln1
        layernorm_kernel<<<NT, 256>>>(x, h, ln1g + (size_t)l*CD, ln1b + (size_t)l*CD);

        // 3. fused qkv weight transpose -> (D, 3072)
        {
            int tot4 = 3 * (CD * CD) / 4;
            transpose_w3<<<(tot4 + 255) / 256, 256>>>(wq + wOff, wk + wOff, wv + wOff, wt);
        }

        // 4. fused QKV projection: (4096 x 1024) @ (1024 x 3072)
        {
            dim3 grid(NT / 128, CQKV / 128, 1);
            hgemm<0,0><<<grid, 256>>>(h, CD, 0, 0, wt, CQKV, 0, 0,
                                      qkv, CQKV, 0, 0,
                                      1, CQKV, CD, nullptr, nullptr, 0);
        }

        // 5. scores S = Q @ K^T per (b,h), causal tile-skip
        {
            dim3 grid(CT / 128, CT / 128, CB * CH);
            hgemm<1,1><<<grid, 256>>>(qkv,      CQKV, TQ, CHS,
                                      qkv + CD, CQKV, TQ, CHS,
                                      s, CT, (long long)CH * TT, TT,
                                      CH, CT, CHS, nullptr, nullptr, 0);
        }

        // 6. causal softmax
        softmax_causal<<<CB * CH * CT, 128>>>(s);

        // 7. O = P @ V per (b,h), causal K-limit (N=64, guarded)
        {
            dim3 grid(CT / 128, 1, CB * CH);
            hgemm<0,2><<<grid, 256>>>(s, CT, (long long)CH * TT, TT,
                                      qkv + 2 * CD, CQKV, TQ, CHS,
                                      o, CD, TD, CHS,
                                      CH, CHS, CT, nullptr, nullptr, 0);
        }

        // 8. out projection + bias + residual
        {
            dim3 grid(NT / 128, CD / 128, 1);
            hgemm<0,0><<<grid, 256>>>(o, CD, 0, 0, wprj + (size_t)l*CD*CD, CD, 0, 0,
                                      x, CD, 0, 0, 1, CD, CD,
                                      bprj + (size_t)l*CD, x, 0);
        }

        // 9. ln2
        layernorm_kernel<<<NT, 256>>>(x, h, ln2g + (size_t)l*CD, ln2b + (size_t)l*CD);

        // 10. FFN up + relu
        {
            dim3 grid(NT / 128, CFF / 128, 1);
            hgemm<0,0><<<grid, 256>>>(h, CD, 0, 0, w1 + (size_t)l*CD*CFF, CFF, 0, 0,
                                      ffn, CFF, 0, 0, 1, CFF, CD,
                                      b1 + (size_t)l*CFF, nullptr, 1);
        }

        // 11. FFN down + bias + residual
        {
            dim3 grid(NT / 128, CD / 128, 1);
            hgemm<0,0><<<grid, 256>>>(ffn, CFF, 0, 0, w2 + (size_t)l*CFF*CD, CD, 0, 0,
                                      x, CD, 0, 0, 1, CD, CFF,
                                      b2 + (size_t)l*CD, x, 0);
        }
    }

    // 12. final layernorm
    layernorm_kernel<<<NT, 256>>>(x, h, lnfg, lnfb);

    // 13. logits: (4096 x 1024) @ (1024 x 32000) + b_out
    {
        dim3 grid(NT / 128, CV / 128, 1);
        hgemm<0,0><<<grid, 256>>>(h, CD, 0, 0, wout, CV, 0, 0,
                                  out, CV, 0, 0, 1, CV, CD,
                                  bout, nullptr, 0);
    }
}

// round 14
// speedup vs baseline: 1.0006x; 1.0006x over previous
#include <cuda_runtime.h>
#include <cuda_fp16.h>
#include <cstdint>
#include <cstddef>

#define CB 4
#define CT 1024
#define CD 1024
#define CH 16
#define CHS 64
#define CL 4
#define CFF 4096
#define CV 32000
#define CQKV 3072

// ---------------- scratch (static __device__ arrays; no runtime alloc) ------
__device__ float g_x  [(size_t)CB*CT*CD];
__device__ float g_h  [(size_t)CB*CT*CD];
__device__ float g_qkv[(size_t)CB*CT*CQKV];   // q | k | v concat along cols
__device__ float g_o  [(size_t)CB*CT*CD];
__device__ float g_ffn[(size_t)CB*CT*CFF];
__device__ float g_s  [(size_t)CB*CH*CT*CT];
__device__ float g_wt [(size_t)CD*CQKV];      // (D, 3*H*HS) qkv weights

// ---------------- helpers -----------------------------------------------------
__device__ __forceinline__ uint32_t f2h2(float lo, float hi) {
    uint32_t u;
    asm("cvt.rn.f16x2.f32 %0, %1, %2;" : "=r"(u) : "f"(hi), "f"(lo));
    return u;
}
__device__ __forceinline__ void sts128(uint32_t a, uint32_t u0, uint32_t u1,
                                       uint32_t u2, uint32_t u3) {
    asm volatile("st.shared.v4.b32 [%0], {%1,%2,%3,%4};"
                 :: "r"(a), "r"(u0), "r"(u1), "r"(u2), "r"(u3));
}
__device__ __forceinline__ uint32_t smem_u32(const void* p) {
    uint32_t a;
    asm("{ .reg .u64 t; cvta.to.shared.u64 t, %1; cvt.u32.u64 %0, t; }"
        : "=r"(a) : "l"(p));
    return a;
}
__device__ __forceinline__ void mma_f16(float* c,
    uint32_t a0, uint32_t a1, uint32_t a2, uint32_t a3,
    uint32_t b0, uint32_t b1)
{
    asm volatile(
        "mma.sync.aligned.m16n8k16.row.col.f32.f16.f16.f32 "
        "{%0,%1,%2,%3}, {%4,%5,%6,%7}, {%8,%9}, {%0,%1,%2,%3};"
        : "+f"(c[0]), "+f"(c[1]), "+f"(c[2]), "+f"(c[3])
        : "r"(a0), "r"(a1), "r"(a2), "r"(a3), "r"(b0), "r"(b1));
}

// ================= fp16 tensor-core GEMM ======================================
// C[M,N] = A[M,K] @ op(B) (+bias) (+res) (relu), fp32 in/out, fp16 compute.
// NTB=0: B gmem [K,N] row-major.  NTB=1: B gmem [N,K] row-major (C = A B^T).
// CMODE: 0 none; 1 causal tile-skip (scores); 2 causal K-limit (AV).
// Block tile 128x128, K-chunk 32. Requires M%128==0, K%32==0; N guarded.
// grid: x = M/128 (fast), y = ceil(N/128), z = batch.
// Batch: X += (z/hdiv)*sXo + (z%hdiv)*sXi.
template<int NTB, int CMODE>
__global__ __launch_bounds__(256, 2) void hgemm(
    const float* __restrict__ A, int lda, long long sAo, long long sAi,
    const float* __restrict__ B, int ldb, long long sBo, long long sBi,
    float* __restrict__ C, int ldc, long long sCo, long long sCi,
    int hdiv, int N, int K,
    const float* __restrict__ bias, const float* __restrict__ res, int relu)
{
    const int m0 = blockIdx.x * 128, n0 = blockIdx.y * 128;
    if (CMODE == 1 && n0 > m0 + 127) return;

    long long z = blockIdx.z, zo = z / hdiv, zi = z % hdiv;
    A += zo * sAo + zi * sAi;
    B += zo * sBo + zi * sBi;
    C += zo * sCo + zi * sCi;
    const float* resp = res ? (res + zo * sCo + zi * sCi) : nullptr;

    // smem: 128 rows x 16 half2 (K=32 halves), stride 20 half2 (conflict-free)
    __shared__ uint32_t As[128 * 20];
    __shared__ uint32_t Bs[128 * 20];
    const uint32_t aBase = smem_u32(As), bBase = smem_u32(Bs);

    const int tid  = threadIdx.x;
    const int lane = tid & 31, wid = tid >> 5;
    const int wm = wid & 1, wn = wid >> 1;      // 2 x 4 warp grid
    const int g = lane >> 2, q = lane & 3;

    // -------- producer indices --------
    const int ar = tid >> 1;                    // 0..127 (row)
    const int kb = (tid & 1) * 16;              // float k offset within chunk
    const int ks = (tid & 1) * 8;               // half2 col offset
    const float* Ap = A + (size_t)(m0 + ar) * lda + kb;

    const float* Bp;
    int nn = 0, kb2 = 0, bok = 1;
    if (NTB) {
        Bp = B + (size_t)(n0 + ar) * ldb + kb;
        bok = (n0 + ar) < N;
    } else {
        nn  = tid & 127;
        kb2 = (tid >> 7) * 16;
        Bp  = B + (size_t)kb2 * ldb + n0 + nn;
        bok = (n0 + nn) < N;
    }

    int KL = K;
    if (CMODE == 2) { int kl = m0 + 128; if (kl < KL) KL = kl; }

    float acc[4][4][4];
    #pragma unroll
    for (int i = 0; i < 4; i++)
        #pragma unroll
        for (int j = 0; j < 4; j++)
            #pragma unroll
            for (int e = 0; e < 4; e++) acc[i][j][e] = 0.f;

    float4 ra[4], rbt[4];
    float  rbn[16];

    auto loadAB = [&]() {
        #pragma unroll
        for (int j = 0; j < 4; j++) ra[j] = *(const float4*)(Ap + 4 * j);
        if (NTB) {
            if (bok) {
                #pragma unroll
                for (int j = 0; j < 4; j++) rbt[j] = *(const float4*)(Bp + 4 * j);
            } else {
                #pragma unroll
                for (int j = 0; j < 4; j++) rbt[j] = make_float4(0.f, 0.f, 0.f, 0.f);
            }
        } else {
            #pragma unroll
            for (int j = 0; j < 16; j++)
                rbn[j] = bok ? Bp[(size_t)j * ldb] : 0.f;
        }
    };
    auto storeAB = [&]() {
        uint32_t h[8];
        #pragma unroll
        for (int j = 0; j < 4; j++) {
            h[2*j]   = f2h2(ra[j].x, ra[j].y);
            h[2*j+1] = f2h2(ra[j].z, ra[j].w);
        }
        uint32_t aoff = aBase + (uint32_t)(ar * 20 + ks) * 4;
        sts128(aoff,      h[0], h[1], h[2], h[3]);
        sts128(aoff + 16, h[4], h[5], h[6], h[7]);
        if (NTB) {
            #pragma unroll
            for (int j = 0; j < 4; j++) {
                h[2*j]   = f2h2(rbt[j].x, rbt[j].y);
                h[2*j+1] = f2h2(rbt[j].z, rbt[j].w);
            }
            uint32_t boff = bBase + (uint32_t)(ar * 20 + ks) * 4;
            sts128(boff,      h[0], h[1], h[2], h[3]);
            sts128(boff + 16, h[4], h[5], h[6], h[7]);
        } else {
            #pragma unroll
            for (int j = 0; j < 8; j++) h[j] = f2h2(rbn[2*j], rbn[2*j+1]);
            uint32_t boff = bBase + (uint32_t)(nn * 20 + (kb2 >> 1)) * 4;
            sts128(boff,      h[0], h[1], h[2], h[3]);
            sts128(boff + 16, h[4], h[5], h[6], h[7]);
        }
    };

    // prologue: chunk kk=0
    loadAB();
    storeAB();
    __syncthreads();

    for (int kk = 32;; kk += 32) {
        const bool more = kk < KL;
        if (more) {
            Ap += 32;
            if (NTB) Bp += 32;
            else     Bp += (size_t)32 * ldb;
            loadAB();
        }

        #pragma unroll
        for (int s = 0; s < 2; s++) {
            const int q0 = s * 8;
            uint32_t af[4][4], bf[4][2];
            #pragma unroll
            for (int mi = 0; mi < 4; mi++) {
                int base = (wm * 64 + mi * 16 + g) * 20 + q0 + q;
                af[mi][0] = As[base];
                af[mi][1] = As[base + 160];
                af[mi][2] = As[base + 4];
                af[mi][3] = As[base + 164];
            }
            #pragma unroll
            for (int ni = 0; ni < 4; ni++) {
                int base = (wn * 32 + ni * 8 + g) * 20 + q0 + q;
                bf[ni][0] = Bs[base];
                bf[ni][1] = Bs[base + 4];
            }
            #pragma unroll
            for (int mi = 0; mi < 4; mi++)
                #pragma unroll
                for (int ni = 0; ni < 4; ni++)
                    mma_f16(acc[mi][ni], af[mi][0], af[mi][1], af[mi][2], af[mi][3],
                            bf[ni][0], bf[ni][1]);
        }

        if (!more) break;
        __syncthreads();
        storeAB();
        __syncthreads();
    }

    // -------- epilogue --------
    #pragma unroll
    for (int mi = 0; mi < 4; mi++) {
        int r0 = m0 + wm * 64 + mi * 16 + g;
        #pragma unroll
        for (int ni = 0; ni < 4; ni++) {
            int c0 = n0 + wn * 32 + ni * 8 + (q << 1);
            if (c0 >= N) continue;
            float b0 = 0.f, b1 = 0.f;
            if (bias) { b0 = bias[c0]; b1 = bias[c0 + 1]; }
            float v0 = acc[mi][ni][0] + b0, v1 = acc[mi][ni][1] + b1;
            float v2 = acc[mi][ni][2] + b0, v3 = acc[mi][ni][3] + b1;
            size_t o0 = (size_t)r0 * ldc + c0;
            size_t o1 = (size_t)(r0 + 8) * ldc + c0;
            if (resp) {
                float2 x0 = *(const float2*)(resp + o0); v0 += x0.x; v1 += x0.y;
                float2 x1 = *(const float2*)(resp + o1); v2 += x1.x; v3 += x1.y;
            }
            if (relu) {
                v0 = fmaxf(v0, 0.f); v1 = fmaxf(v1, 0.f);
                v2 = fmaxf(v2, 0.f); v3 = fmaxf(v3, 0.f);
            }
            float2 s0; s0.x = v0; s0.y = v1;
            float2 s1; s1.x = v2; s1.y = v3;
            *(float2*)(C + o0) = s0;
            *(float2*)(C + o1) = s1;
        }
    }
}

// ---------------- embedding -------------------------------------------------
__global__ void embed_kernel(const int* __restrict__ ids,
                             const float* __restrict__ te,
                             const float* __restrict__ pe,
                             float* __restrict__ x)
{
    size_t i = (size_t)blockIdx.x * blockDim.x + threadIdx.x;
    if (i >= (size_t)CB*CT*CD) return;
    int d = (int)(i % CD);
    size_t bt = i / CD;
    int t = (int)(bt % CT);
    x[i] = te[(size_t)ids[bt]*CD + d] + pe[(size_t)t*CD + d];
}

// ---------------- layernorm --------------------------------------------------
__global__ void layernorm_kernel(const float* __restrict__ x, float* __restrict__ y,
                                 const float* __restrict__ g, const float* __restrict__ bb)
{
    int row = blockIdx.x;
    const float* xr = x + (size_t)row * CD;
    float* yr = y + (size_t)row * CD;
    float s = 0.f, s2 = 0.f;
    for (int i = threadIdx.x; i < CD; i += blockDim.x) {
        float u = xr[i]; s += u; s2 += u*u;
    }
    __shared__ float rs[32], rs2[32], stats[2];
    #pragma unroll
    for (int o = 16; o; o >>= 1) {
        s  += __shfl_xor_sync(0xffffffffu, s,  o);
        s2 += __shfl_xor_sync(0xffffffffu, s2, o);
    }
    int wid = threadIdx.x >> 5;
    if ((threadIdx.x & 31) == 0) { rs[wid] = s; rs2[wid] = s2; }
    __syncthreads();
    if (threadIdx.x == 0) {
        float ts = 0.f, ts2 = 0.f;
        int nw = blockDim.x >> 5;
        for (int i = 0; i < nw; i++) { ts += rs[i]; ts2 += rs2[i]; }
        float m = ts / (float)CD;
        float var = ts2 / (float)CD - m*m;
        stats[0] = m; stats[1] = rsqrtf(var + 1e-5f);
    }
    __syncthreads();
    float m = stats[0], r = stats[1];
    for (int i = threadIdx.x; i < CD; i += blockDim.x)
        yr[i] = (xr[i] - m) * r * g[i] + bb[i];
}

// ---- fused wq/wk/wv transpose: 3 x (H,D,HS) -> (D, 3*H*HS) ld=3072 ----------
__global__ void transpose_w3(const float* __restrict__ wq,
                             const float* __restrict__ wk,
                             const float* __restrict__ wv,
                             float* __restrict__ dst)
{
    int fid = blockIdx.x * blockDim.x + threadIdx.x;  // float4 index
    const int per = (CD * CD) >> 2;                    // 262144
    if (fid >= 3 * per) return;
    int w = fid / per, r = fid - w * per;
    int d = r >> 8, rem = r & 255, hh = rem >> 4, e4 = (rem & 15) << 2;
    const float* src = (w == 0) ? wq : ((w == 1) ? wk : wv);
    float4 v = *(const float4*)(src + ((size_t)hh * CD + d) * CHS + e4);
    *(float4*)(dst + (size_t)d * CQKV + w * CD + hh * CHS + e4) = v;
}

// ---------------- causal softmax; zeros only to next 128 boundary ------------
__global__ void softmax_causal(float* __restrict__ S)
{
    int row = blockIdx.x;          // (b*H+h)*T + t
    int t = row & (CT - 1);
    float* p = S + (size_t)row * CT;
    int n = t + 1;
    const float scale = 0.03125f;  // 1024^-0.5

    __shared__ float red[32];
    __shared__ float bval;

    float m = -1e30f;
    for (int j = threadIdx.x; j < n; j += blockDim.x) m = fmaxf(m, p[j] * scale);
    #pragma unroll
    for (int o = 16; o; o >>= 1) m = fmaxf(m, __shfl_xor_sync(0xffffffffu, m, o));
    int wid = threadIdx.x >> 5;
    if ((threadIdx.x & 31) == 0) red[wid] = m;
    __syncthreads();
    if (threadIdx.x == 0) {
        float mm = -1e30f; int nw = blockDim.x >> 5;
        for (int i = 0; i < nw; i++) mm = fmaxf(mm, red[i]);
        bval = mm;
    }
    __syncthreads();
    float bmax = bval;

    float s = 0.f;
    for (int j = threadIdx.x; j < n; j += blockDim.x) {
        float e = __expf(p[j] * scale - bmax);
        p[j] = e; s += e;
    }
    __syncthreads();
    #pragma unroll
    for (int o = 16; o; o >>= 1) s += __shfl_xor_sync(0xffffffffu, s, o);
    if ((threadIdx.x & 31) == 0) red[wid] = s;
    __syncthreads();
    if (threadIdx.x == 0) {
        float ss = 0.f; int nw = blockDim.x >> 5;
        for (int i = 0; i < nw; i++) ss += red[i];
        bval = ss;
    }
    __syncthreads();
    float inv = 1.f / bval;
    for (int j = threadIdx.x; j < n; j += blockDim.x) p[j] *= inv;
    int zend = ((t >> 7) + 1) << 7;    // AV reads k < m0+128 only
    for (int j = n + threadIdx.x; j < zend; j += blockDim.x) p[j] = 0.f;
}

// ---------------- host orchestration ----------------------------------------
extern "C" void kernel_launch(void* const* d_in, const int* in_sizes, int n_in,
                              void* d_out, int out_size)
{
    (void)in_sizes; (void)n_in; (void)out_size;
    const int*   ids  = (const int*)  d_in[0];
    const float* tok  = (const float*)d_in[1];
    const float* pos  = (const float*)d_in[2];
    const float* wq   = (const float*)d_in[3];
    const float* wk   = (const float*)d_in[4];
    const float* wv   = (const float*)d_in[5];
    const float* wprj = (const float*)d_in[6];
    const float* bprj = (const float*)d_in[7];
    const float* ln1g = (const float*)d_in[8];
    const float* ln1b = (const float*)d_in[9];
    const float* ln2g = (const float*)d_in[10];
    const float* ln2b = (const float*)d_in[11];
    const float* w1   = (const float*)d_in[12];
    const float* b1   = (const float*)d_in[13];
    const float* w2   = (const float*)d_in[14];
    const float* b2   = (const float*)d_in[15];
    const float* lnfg = (const float*)d_in[16];
    const float* lnfb = (const float*)d_in[17];
    const float* wout = (const float*)d_in[18];
    const float* bout = (const float*)d_in[19];
    float* out = (float*)d_out;

    float *x, *h, *qkv, *o, *ffn, *s, *wt;
    cudaGetSymbolAddress((void**)&x,   g_x);
    cudaGetSymbolAddress((void**)&h,   g_h);
    cudaGetSymbolAddress((void**)&qkv, g_qkv);
    cudaGetSymbolAddress((void**)&o,   g_o);
    cudaGetSymbolAddress((void**)&ffn, g_ffn);
    cudaGetSymbolAddress((void**)&s,   g_s);
    cudaGetSymbolAddress((void**)&wt,  g_wt);

    const int NT = CB * CT;                       // 4096 rows
    const long long TQ = (long long)CT * CQKV;    // qkv batch stride (per b)
    const long long TD = (long long)CT * CD;
    const long long TT = (long long)CT * CT;

    // 1. embedding
    {
        size_t tot = (size_t)CB * CT * CD;
        embed_kernel<<<(unsigned)((tot + 255) / 256), 256>>>(ids, tok, pos, x);
    }

    for (int l = 0; l < CL; l++) {
        const size_t wOff = (size_t)l * CD * CD;

        // 2. ln1
        layernorm_kernel<<<NT, 256>>>(x, h, ln1g + (size_t)l*CD, ln1b + (size_t)l*CD);

        // 3. fused qkv weight transpose -> (D, 3072)
        {
            int tot4 = 3 * (CD * CD) / 4;
            transpose_w3<<<(tot4 + 255) / 256, 256>>>(wq + wOff, wk + wOff, wv + wOff, wt);
        }

        // 4. fused QKV projection: (4096 x 1024) @ (1024 x 3072)
        {
            dim3 grid(NT / 128, CQKV / 128, 1);
            hgemm<0,0><<<grid, 256>>>(h, CD, 0, 0, wt, CQKV, 0, 0,
                                      qkv, CQKV, 0, 0,
                                      1, CQKV, CD, nullptr, nullptr, 0);
        }

        // 5. scores S = Q @ K^T per (b,h), causal tile-skip
        {
            dim3 grid(CT / 128, CT / 128, CB * CH);
            hgemm<1,1><<<grid, 256>>>(qkv,      CQKV, TQ, CHS,
                                      qkv + CD, CQKV, TQ, CHS,
                                      s, CT, (long long)CH * TT, TT,
                                      CH, CT, CHS, nullptr, nullptr, 0);
        }

        // 6. causal softmax
        softmax_causal<<<CB * CH * CT, 128>>>(s);

        // 7. O = P @ V per (b,h), causal K-limit (N=64, guarded)
        {
            dim3 grid(CT / 128, 1, CB * CH);
            hgemm<0,2><<<grid, 256>>>(s, CT, (long long)CH * TT, TT,
                                      qkv + 2 * CD, CQKV, TQ, CHS,
                                      o, CD, TD, CHS,
                                      CH, CHS, CT, nullptr, nullptr, 0);
        }

        // 8. out projection + bias + residual
        {
            dim3 grid(NT / 128, CD / 128, 1);
            hgemm<0,0><<<grid, 256>>>(o, CD, 0, 0, wprj + (size_t)l*CD*CD, CD, 0, 0,
                                      x, CD, 0, 0, 1, CD, CD,
                                      bprj + (size_t)l*CD, x, 0);
        }

        // 9. ln2
        layernorm_kernel<<<NT, 256>>>(x, h, ln2g + (size_t)l*CD, ln2b + (size_t)l*CD);

        // 10. FFN up + relu
        {
            dim3 grid(NT / 128, CFF / 128, 1);
            hgemm<0,0><<<grid, 256>>>(h, CD, 0, 0, w1 + (size_t)l*CD*CFF, CFF, 0, 0,
                                      ffn, CFF, 0, 0, 1, CFF, CD,
                                      b1 + (size_t)l*CFF, nullptr, 1);
        }

        // 11. FFN down + bias + residual
        {
            dim3 grid(NT / 128, CD / 128, 1);
            hgemm<0,0><<<grid, 256>>>(ffn, CFF, 0, 0, w2 + (size_t)l*CFF*CD, CD, 0, 0,
                                      x, CD, 0, 0, 1, CD, CFF,
                                      b2 + (size_t)l*CD, x, 0);
        }
    }

    // 12. final layernorm
    layernorm_kernel<<<NT, 256>>>(x, h, lnfg, lnfb);

    // 13. logits: (4096 x 1024) @ (1024 x 32000) + b_out
    {
        dim3 grid(NT / 128, CV / 128, 1);
        hgemm<0,0><<<grid, 256>>>(h, CD, 0, 0, wout, CV, 0, 0,
                                  out, CV, 0, 0, 1, CV, CD,
                                  bout, nullptr, 0);
    }
}

// round 15
// speedup vs baseline: 1.0009x; 1.0003x over previous
#include <cuda_runtime.h>
#include <cuda_fp16.h>
#include <cstdint>
#include <cstddef>

#define CB 4
#define CT 1024
#define CD 1024
#define CH 16
#define CHS 64
#define CL 4
#define CFF 4096
#define CV 32000
#define CQKV 3072

// ---------------- scratch (static __device__ arrays; no runtime alloc) ------
__device__ float g_x  [(size_t)CB*CT*CD];
__device__ float g_h  [(size_t)CB*CT*CD];
__device__ float g_qkv[(size_t)CB*CT*CQKV];   // q | k | v concat along cols
__device__ float g_o  [(size_t)CB*CT*CD];
__device__ float g_ffn[(size_t)CB*CT*CFF];
__device__ float g_s  [(size_t)CB*CH*CT*CT];
__device__ float g_wt [(size_t)CD*CQKV];      // (D, 3*H*HS) qkv weights

// ---------------- helpers -----------------------------------------------------
__device__ __forceinline__ uint32_t f2h2(float lo, float hi) {
    uint32_t u;
    asm("cvt.rn.f16x2.f32 %0, %1, %2;" : "=r"(u) : "f"(hi), "f"(lo));
    return u;
}
__device__ __forceinline__ void sts128(uint32_t a, uint32_t u0, uint32_t u1,
                                       uint32_t u2, uint32_t u3) {
    asm volatile("st.shared.v4.b32 [%0], {%1,%2,%3,%4};"
                 :: "r"(a), "r"(u0), "r"(u1), "r"(u2), "r"(u3));
}
__device__ __forceinline__ uint32_t smem_u32(const void* p) {
    uint32_t a;
    asm("{ .reg .u64 t; cvta.to.shared.u64 t, %1; cvt.u32.u64 %0, t; }"
        : "=r"(a) : "l"(p));
    return a;
}
__device__ __forceinline__ void mma_f16(float* c,
    uint32_t a0, uint32_t a1, uint32_t a2, uint32_t a3,
    uint32_t b0, uint32_t b1)
{
    asm volatile(
        "mma.sync.aligned.m16n8k16.row.col.f32.f16.f16.f32 "
        "{%0,%1,%2,%3}, {%4,%5,%6,%7}, {%8,%9}, {%0,%1,%2,%3};"
        : "+f"(c[0]), "+f"(c[1]), "+f"(c[2]), "+f"(c[3])
        : "r"(a0), "r"(a1), "r"(a2), "r"(a3), "r"(b0), "r"(b1));
}

// ================= fp16 tensor-core GEMM ======================================
// C[M,N] = A[M,K] @ op(B) (+bias) (+res) (relu), fp32 in/out, fp16 compute.
// NTB=0: B gmem [K,N] row-major.  NTB=1: B gmem [N,K] row-major (C = A B^T).
// CMODE: 0 none; 1 causal tile-skip (scores); 2 causal K-limit (AV).
// Block tile 128x128, K-chunk 32. Requires M%128==0, K%32==0; N guarded.
// grid: x = M/128 (fast), y = ceil(N/128), z = batch.
// Batch: X += (z/hdiv)*sXo + (z%hdiv)*sXi.
template<int NTB, int CMODE>
__global__ __launch_bounds__(256, 2) void hgemm(
    const float* __restrict__ A, int lda, long long sAo, long long sAi,
    const float* __restrict__ B, int ldb, long long sBo, long long sBi,
    float* __restrict__ C, int ldc, long long sCo, long long sCi,
    int hdiv, int N, int K,
    const float* __restrict__ bias, const float* __restrict__ res, int relu)
{
    const int m0 = blockIdx.x * 128, n0 = blockIdx.y * 128;
    if (CMODE == 1 && n0 > m0 + 127) return;

    long long z = blockIdx.z, zo = z / hdiv, zi = z % hdiv;
    A += zo * sAo + zi * sAi;
    B += zo * sBo + zi * sBi;
    C += zo * sCo + zi * sCi;
    const float* resp = res ? (res + zo * sCo + zi * sCi) : nullptr;

    // smem: 128 rows x 16 half2 (K=32 halves), stride 20 half2 (conflict-free)
    __shared__ uint32_t As[128 * 20];
    __shared__ uint32_t Bs[128 * 20];
    const uint32_t aBase = smem_u32(As), bBase = smem_u32(Bs);

    const int tid  = threadIdx.x;
    const int lane = tid & 31, wid = tid >> 5;
    const int wm = wid & 1, wn = wid >> 1;      // 2 x 4 warp grid
    const int g = lane >> 2, q = lane & 3;

    // -------- producer indices --------
    const int ar = tid >> 1;                    // 0..127 (row)
    const int kb = (tid & 1) * 16;              // float k offset within chunk
    const int ks = (tid & 1) * 8;               // half2 col offset
    const float* Ap = A + (size_t)(m0 + ar) * lda + kb;

    const float* Bp;
    int nn = 0, kb2 = 0, bok = 1;
    if (NTB) {
        Bp = B + (size_t)(n0 + ar) * ldb + kb;
        bok = (n0 + ar) < N;
    } else {
        nn  = tid & 127;
        kb2 = (tid >> 7) * 16;
        Bp  = B + (size_t)kb2 * ldb + n0 + nn;
        bok = (n0 + nn) < N;
    }

    int KL = K;
    if (CMODE == 2) { int kl = m0 + 128; if (kl < KL) KL = kl; }

    float acc[4][4][4];
    #pragma unroll
    for (int i = 0; i < 4; i++)
        #pragma unroll
        for (int j = 0; j < 4; j++)
            #pragma unroll
            for (int e = 0; e < 4; e++) acc[i][j][e] = 0.f;

    float4 ra[4], rbt[4];
    float  rbn[16];

    auto loadAB = [&]() {
        #pragma unroll
        for (int j = 0; j < 4; j++) ra[j] = *(const float4*)(Ap + 4 * j);
        if (NTB) {
            if (bok) {
                #pragma unroll
                for (int j = 0; j < 4; j++) rbt[j] = *(const float4*)(Bp + 4 * j);
            } else {
                #pragma unroll
                for (int j = 0; j < 4; j++) rbt[j] = make_float4(0.f, 0.f, 0.f, 0.f);
            }
        } else {
            #pragma unroll
            for (int j = 0; j < 16; j++)
                rbn[j] = bok ? Bp[(size_t)j * ldb] : 0.f;
        }
    };
    auto storeAB = [&]() {
        uint32_t h[8];
        #pragma unroll
        for (int j = 0; j < 4; j++) {
            h[2*j]   = f2h2(ra[j].x, ra[j].y);
            h[2*j+1] = f2h2(ra[j].z, ra[j].w);
        }
        uint32_t aoff = aBase + (uint32_t)(ar * 20 + ks) * 4;
        sts128(aoff,      h[0], h[1], h[2], h[3]);
        sts128(aoff + 16, h[4], h[5], h[6], h[7]);
        if (NTB) {
            #pragma unroll
            for (int j = 0; j < 4; j++) {
                h[2*j]   = f2h2(rbt[j].x, rbt[j].y);
                h[2*j+1] = f2h2(rbt[j].z, rbt[j].w);
            }
            uint32_t boff = bBase + (uint32_t)(ar * 20 + ks) * 4;
            sts128(boff,      h[0], h[1], h[2], h[3]);
            sts128(boff + 16, h[4], h[5], h[6], h[7]);
        } else {
            #pragma unroll
            for (int j = 0; j < 8; j++) h[j] = f2h2(rbn[2*j], rbn[2*j+1]);
            uint32_t boff = bBase + (uint32_t)(nn * 20 + (kb2 >> 1)) * 4;
            sts128(boff,      h[0], h[1], h[2], h[3]);
            sts128(boff + 16, h[4], h[5], h[6], h[7]);
        }
    };

    // prologue: chunk kk=0
    loadAB();
    storeAB();
    __syncthreads();

    for (int kk = 32;; kk += 32) {
        const bool more = kk < KL;
        if (more) {
            Ap += 32;
            if (NTB) Bp += 32;
            else     Bp += (size_t)32 * ldb;
            loadAB();
        }

        #pragma unroll
        for (int s = 0; s < 2; s++) {
            const int q0 = s * 8;
            uint32_t af[4][4], bf[4][2];
            #pragma unroll
            for (int mi = 0; mi < 4; mi++) {
                int base = (wm * 64 + mi * 16 + g) * 20 + q0 + q;
                af[mi][0] = As[base];
                af[mi][1] = As[base + 160];
                af[mi][2] = As[base + 4];
                af[mi][3] = As[base + 164];
            }
            #pragma unroll
            for (int ni = 0; ni < 4; ni++) {
                int base = (wn * 32 + ni * 8 + g) * 20 + q0 + q;
                bf[ni][0] = Bs[base];
                bf[ni][1] = Bs[base + 4];
            }
            #pragma unroll
            for (int mi = 0; mi < 4; mi++)
                #pragma unroll
                for (int ni = 0; ni < 4; ni++)
                    mma_f16(acc[mi][ni], af[mi][0], af[mi][1], af[mi][2], af[mi][3],
                            bf[ni][0], bf[ni][1]);
        }

        if (!more) break;
        __syncthreads();
        storeAB();
        __syncthreads();
    }

    // -------- epilogue --------
    #pragma unroll
    for (int mi = 0; mi < 4; mi++) {
        int r0 = m0 + wm * 64 + mi * 16 + g;
        #pragma unroll
        for (int ni = 0; ni < 4; ni++) {
            int c0 = n0 + wn * 32 + ni * 8 + (q << 1);
            if (c0 >= N) continue;
            float b0 = 0.f, b1 = 0.f;
            if (bias) { b0 = bias[c0]; b1 = bias[c0 + 1]; }
            float v0 = acc[mi][ni][0] + b0, v1 = acc[mi][ni][1] + b1;
            float v2 = acc[mi][ni][2] + b0, v3 = acc[mi][ni][3] + b1;
            size_t o0 = (size_t)r0 * ldc + c0;
            size_t o1 = (size_t)(r0 + 8) * ldc + c0;
            if (resp) {
                float2 x0 = *(const float2*)(resp + o0); v0 += x0.x; v1 += x0.y;
                float2 x1 = *(const float2*)(resp + o1); v2 += x1.x; v3 += x1.y;
            }
            if (relu) {
                v0 = fmaxf(v0, 0.f); v1 = fmaxf(v1, 0.f);
                v2 = fmaxf(v2, 0.f); v3 = fmaxf(v3, 0.f);
            }
            float2 s0; s0.x = v0; s0.y = v1;
            float2 s1; s1.x = v2; s1.y = v3;
            *(float2*)(C + o0) = s0;
            *(float2*)(C + o1) = s1;
        }
    }
}

// ---------------- embedding -------------------------------------------------
__global__ void embed_kernel(const int* __restrict__ ids,
                             const float* __restrict__ te,
                             const float* __restrict__ pe,
                             float* __restrict__ x)
{
    size_t i = (size_t)blockIdx.x * blockDim.x + threadIdx.x;
    if (i >= (size_t)CB*CT*CD) return;
    int d = (int)(i % CD);
    size_t bt = i / CD;
    int t = (int)(bt % CT);
    x[i] = te[(size_t)ids[bt]*CD + d] + pe[(size_t)t*CD + d];
}

// ---------------- layernorm --------------------------------------------------
__global__ void layernorm_kernel(const float* __restrict__ x, float* __restrict__ y,
                                 const float* __restrict__ g, const float* __restrict__ bb)
{
    int row = blockIdx.x;
    const float* xr = x + (size_t)row * CD;
    float* yr = y + (size_t)row * CD;
    float s = 0.f, s2 = 0.f;
    for (int i = threadIdx.x; i < CD; i += blockDim.x) {
        float u = xr[i]; s += u; s2 += u*u;
    }
    __shared__ float rs[32], rs2[32], stats[2];
    #pragma unroll
    for (int o = 16; o; o >>= 1) {
        s  += __shfl_xor_sync(0xffffffffu, s,  o);
        s2 += __shfl_xor_sync(0xffffffffu, s2, o);
    }
    int wid = threadIdx.x >> 5;
    if ((threadIdx.x & 31) == 0) { rs[wid] = s; rs2[wid] = s2; }
    __syncthreads();
    if (threadIdx.x == 0) {
        float ts = 0.f, ts2 = 0.f;
        int nw = blockDim.x >> 5;
        for (int i = 0; i < nw; i++) { ts += rs[i]; ts2 += rs2[i]; }
        float m = ts / (float)CD;
        float var = ts2 / (float)CD - m*m;
        stats[0] = m; stats[1] = rsqrtf(var + 1e-5f);
    }
    __syncthreads();
    float m = stats[0], r = stats[1];
    for (int i = threadIdx.x; i < CD; i += blockDim.x)
        yr[i] = (xr[i] - m) * r * g[i] + bb[i];
}

// ---- fused wq/wk/wv transpose: 3 x (H,D,HS) -> (D, 3*H*HS) ld=3072 ----------
__global__ void transpose_w3(const float* __restrict__ wq,
                             const float* __restrict__ wk,
                             const float* __restrict__ wv,
                             float* __restrict__ dst)
{
    int fid = blockIdx.x * blockDim.x + threadIdx.x;  // float4 index
    const int per = (CD * CD) >> 2;                    // 262144
    if (fid >= 3 * per) return;
    int w = fid / per, r = fid - w * per;
    int d = r >> 8, rem = r & 255, hh = rem >> 4, e4 = (rem & 15) << 2;
    const float* src = (w == 0) ? wq : ((w == 1) ? wk : wv);
    float4 v = *(const float4*)(src + ((size_t)hh * CD + d) * CHS + e4);
    *(float4*)(dst + (size_t)d * CQKV + w * CD + hh * CHS + e4) = v;
}

// ---------------- causal softmax; zeros only to next 128 boundary ------------
__global__ void softmax_causal(float* __restrict__ S)
{
    int row = blockIdx.x;          // (b*H+h)*T + t
    int t = row & (CT - 1);
    float* p = S + (size_t)row * CT;
    int n = t + 1;
    const float scale = 0.03125f;  // 1024^-0.5

    __shared__ float red[32];
    __shared__ float bval;

    float m = -1e30f;
    for (int j = threadIdx.x; j < n; j += blockDim.x) m = fmaxf(m, p[j] * scale);
    #pragma unroll
    for (int o = 16; o; o >>= 1) m = fmaxf(m, __shfl_xor_sync(0xffffffffu, m, o));
    int wid = threadIdx.x >> 5;
    if ((threadIdx.x & 31) == 0) red[wid] = m;
    __syncthreads();
    if (threadIdx.x == 0) {
        float mm = -1e30f; int nw = blockDim.x >> 5;
        for (int i = 0; i < nw; i++) mm = fmaxf(mm, red[i]);
        bval = mm;
    }
    __syncthreads();
    float bmax = bval;

    float s = 0.f;
    for (int j = threadIdx.x; j < n; j += blockDim.x) {
        float e = __expf(p[j] * scale - bmax);
        p[j] = e; s += e;
    }
    __syncthreads();
    #pragma unroll
    for (int o = 16; o; o >>= 1) s += __shfl_xor_sync(0xffffffffu, s, o);
    if ((threadIdx.x & 31) == 0) red[wid] = s;
    __syncthreads();
    if (threadIdx.x == 0) {
        float ss = 0.f; int nw = blockDim.x >> 5;
        for (int i = 0; i < nw; i++) ss += red[i];
        bval = ss;
    }
    __syncthreads();
    float inv = 1.f / bval;
    for (int j = threadIdx.x; j < n; j += blockDim.x) p[j] *= inv;
    int zend = ((t >> 7) + 1) << 7;    // AV reads k < m0+128 only
    for (int j = n + threadIdx.x; j < zend; j += blockDim.x) p[j] = 0.f;
}

// ---------------- host orchestration ----------------------------------------
extern "C" void kernel_launch(void* const* d_in, const int* in_sizes, int n_in,
                              void* d_out, int out_size)
{
    (void)in_sizes; (void)n_in; (void)out_size;
    const int*   ids  = (const int*)  d_in[0];
    const float* tok  = (const float*)d_in[1];
    const float* pos  = (const float*)d_in[2];
    const float* wq   = (const float*)d_in[3];
    const float* wk   = (const float*)d_in[4];
    const float* wv   = (const float*)d_in[5];
    const float* wprj = (const float*)d_in[6];
    const float* bprj = (const float*)d_in[7];
    const float* ln1g = (const float*)d_in[8];
    const float* ln1b = (const float*)d_in[9];
    const float* ln2g = (const float*)d_in[10];
    const float* ln2b = (const float*)d_in[11];
    const float* w1   = (const float*)d_in[12];
    const float* b1   = (const float*)d_in[13];
    const float* w2   = (const float*)d_in[14];
    const float* b2   = (const float*)d_in[15];
    const float* lnfg = (const float*)d_in[16];
    const float* lnfb = (const float*)d_in[17];
    const float* wout = (const float*)d_in[18];
    const float* bout = (const float*)d_in[19];
    float* out = (float*)d_out;

    float *x, *h, *qkv, *o, *ffn, *s, *wt;
    cudaGetSymbolAddress((void**)&x,   g_x);
    cudaGetSymbolAddress((void**)&h,   g_h);
    cudaGetSymbolAddress((void**)&qkv, g_qkv);
    cudaGetSymbolAddress((void**)&o,   g_o);
    cudaGetSymbolAddress((void**)&ffn, g_ffn);
    cudaGetSymbolAddress((void**)&s,   g_s);
    cudaGetSymbolAddress((void**)&wt,  g_wt);

    const int NT = CB * CT;                       // 4096 rows
    const long long TQ = (long long)CT * CQKV;    // qkv batch stride (per b)
    const long long TD = (long long)CT * CD;
    const long long TT = (long long)CT * CT;

    // 1. embedding
    {
        size_t tot = (size_t)CB * CT * CD;
        embed_kernel<<<(unsigned)((tot + 255) / 256), 256>>>(ids, tok, pos, x);
    }

    for (int l = 0; l < CL; l++) {
        const size_t wOff = (size_t)l * CD * CD;

        // 2. ln1
        layernorm_kernel<<<NT, 256>>>(x, h, ln1g + (size_t)l*CD, ln1b + (size_t)l*CD);

        // 3. fused qkv weight transpose -> (D, 3072)
        {
            int tot4 = 3 * (CD * CD) / 4;
            transpose_w3<<<(tot4 + 255) / 256, 256>>>(wq + wOff, wk + wOff, wv + wOff, wt);
        }

        // 4. fused QKV projection: (4096 x 1024) @ (1024 x 3072)
        {
            dim3 grid(NT / 128, CQKV / 128, 1);
            hgemm<0,0><<<grid, 256>>>(h, CD, 0, 0, wt, CQKV, 0, 0,
                                      qkv, CQKV, 0, 0,
                                      1, CQKV, CD, nullptr, nullptr, 0);
        }

        // 5. scores S = Q @ K^T per (b,h), causal tile-skip
        {
            dim3 grid(CT / 128, CT / 128, CB * CH);
            hgemm<1,1><<<grid, 256>>>(qkv,      CQKV, TQ, CHS,
                                      qkv + CD, CQKV, TQ, CHS,
                                      s, CT, (long long)CH * TT, TT,
                                      CH, CT, CHS, nullptr, nullptr, 0);
        }

        // 6. causal softmax
        softmax_causal<<<CB * CH * CT, 128>>>(s);

        // 7. O = P @ V per (b,h), causal K-limit (N=64, guarded)
        {
            dim3 grid(CT / 128, 1, CB * CH);
            hgemm<0,2><<<grid, 256>>>(s, CT, (long long)CH * TT, TT,
                                      qkv + 2 * CD, CQKV, TQ, CHS,
                                      o, CD, TD, CHS,
                                      CH, CHS, CT, nullptr, nullptr, 0);
        }

        // 8. out projection + bias + residual
        {
            dim3 grid(NT / 128, CD / 128, 1);
            hgemm<0,0><<<grid, 256>>>(o, CD, 0, 0, wprj + (size_t)l*CD*CD, CD, 0, 0,
                                      x, CD, 0, 0, 1, CD, CD,
                                      bprj + (size_t)l*CD, x, 0);
        }

        // 9. ln2
        layernorm_kernel<<<NT, 256>>>(x, h, ln2g + (size_t)l*CD, ln2b + (size_t)l*CD);

        // 10. FFN up + relu
        {
            dim3 grid(NT / 128, CFF / 128, 1);
            hgemm<0,0><<<grid, 256>>>(h, CD, 0, 0, w1 + (size_t)l*CD*CFF, CFF, 0, 0,
                                      ffn, CFF, 0, 0, 1, CFF, CD,
                                      b1 + (size_t)l*CFF, nullptr, 1);
        }

        // 11. FFN down + bias + residual
        {
            dim3 grid(NT / 128, CD / 128, 1);
            hgemm<0,0><<<grid, 256>>>(ffn, CFF, 0, 0, w2 + (size_t)l*CFF*CD, CD, 0, 0,
                                      x, CD, 0, 0, 1, CD, CFF,
                                      b2 + (size_t)l*CD, x, 0);
        }
    }

    // 12. final layernorm
    layernorm_kernel<<<NT, 256>>>(x, h, lnfg, lnfb);

    // 13. logits: (4096 x 1024) @ (1024 x 32000) + b_out
    {
        dim3 grid(NT / 128, CV / 128, 1);
        hgemm<0,0><<<grid, 256>>>(h, CD, 0, 0, wout, CV, 0, 0,
                                  out, CV, 0, 0, 1, CV, CD,
                                  bout, nullptr, 0);
    }
}

// round 16
// speedup vs baseline: 1.0041x; 1.0031x over previous
#include <cuda_runtime.h>
#include <cuda_fp16.h>
#include <cstdint>
#include <cstddef>

#define CB 4
#define CT 1024
#define CD 1024
#define CH 16
#define CHS 64
#define CL 4
#define CFF 4096
#define CV 32000
#define CQKV 3072

// ---------------- scratch (static __device__ arrays; no runtime alloc) ------
__device__ float g_x  [(size_t)CB*CT*CD];
__device__ float g_h  [(size_t)CB*CT*CD];
__device__ float g_qkv[(size_t)CB*CT*CQKV];   // q | k | v concat along cols
__device__ float g_o  [(size_t)CB*CT*CD];
__device__ float g_ffn[(size_t)CB*CT*CFF];
__device__ float g_s  [(size_t)CB*CH*CT*CT];
__device__ float g_wt [(size_t)CD*CQKV];      // (D, 3*H*HS) qkv weights

// ---------------- helpers -----------------------------------------------------
__device__ __forceinline__ uint32_t f2h2(float lo, float hi) {
    uint32_t u;
    asm("cvt.rn.f16x2.f32 %0, %1, %2;" : "=r"(u) : "f"(hi), "f"(lo));
    return u;
}
__device__ __forceinline__ void sts128(uint32_t a, uint32_t u0, uint32_t u1,
                                       uint32_t u2, uint32_t u3) {
    asm volatile("st.shared.v4.b32 [%0], {%1,%2,%3,%4};"
                 :: "r"(a), "r"(u0), "r"(u1), "r"(u2), "r"(u3));
}
__device__ __forceinline__ uint32_t smem_u32(const void* p) {
    uint32_t a;
    asm("{ .reg .u64 t; cvta.to.shared.u64 t, %1; cvt.u32.u64 %0, t; }"
        : "=r"(a) : "l"(p));
    return a;
}
__device__ __forceinline__ void mma_f16(float* c,
    uint32_t a0, uint32_t a1, uint32_t a2, uint32_t a3,
    uint32_t b0, uint32_t b1)
{
    asm volatile(
        "mma.sync.aligned.m16n8k16.row.col.f32.f16.f16.f32 "
        "{%0,%1,%2,%3}, {%4,%5,%6,%7}, {%8,%9}, {%0,%1,%2,%3};"
        : "+f"(c[0]), "+f"(c[1]), "+f"(c[2]), "+f"(c[3])
        : "r"(a0), "r"(a1), "r"(a2), "r"(a3), "r"(b0), "r"(b1));
}

// ================= fp16 tensor-core GEMM ======================================
// C[M,N] = A[M,K] @ op(B) (+bias) (+res) (relu), fp32 in/out, fp16 compute.
// NTB=0: B gmem [K,N] row-major.  NTB=1: B gmem [N,K] row-major (C = A B^T).
// CMODE: 0 none; 1 causal tile-skip (scores); 2 causal K-limit (AV).
// Block tile 128x128, K-chunk 32. Requires M%128==0, K%32==0; N guarded.
// grid: x = M/128 (fast), y = ceil(N/128), z = batch.
// Batch: X += (z/hdiv)*sXo + (z%hdiv)*sXi.
template<int NTB, int CMODE>
__global__ __launch_bounds__(256, 2) void hgemm(
    const float* __restrict__ A, int lda, long long sAo, long long sAi,
    const float* __restrict__ B, int ldb, long long sBo, long long sBi,
    float* __restrict__ C, int ldc, long long sCo, long long sCi,
    int hdiv, int N, int K,
    const float* __restrict__ bias, const float* __restrict__ res, int relu)
{
    const int m0 = blockIdx.x * 128, n0 = blockIdx.y * 128;
    if (CMODE == 1 && n0 > m0 + 127) return;

    long long z = blockIdx.z, zo = z / hdiv, zi = z % hdiv;
    A += zo * sAo + zi * sAi;
    B += zo * sBo + zi * sBi;
    C += zo * sCo + zi * sCi;
    const float* resp = res ? (res + zo * sCo + zi * sCi) : nullptr;

    // smem: 128 rows x 16 half2 (K=32 halves), stride 20 half2 (conflict-free)
    __shared__ uint32_t As[128 * 20];
    __shared__ uint32_t Bs[128 * 20];
    const uint32_t aBase = smem_u32(As), bBase = smem_u32(Bs);

    const int tid  = threadIdx.x;
    const int lane = tid & 31, wid = tid >> 5;
    const int wm = wid & 1, wn = wid >> 1;      // 2 x 4 warp grid
    const int g = lane >> 2, q = lane & 3;

    // -------- producer indices --------
    const int ar = tid >> 1;                    // 0..127 (row)
    const int kb = (tid & 1) * 16;              // float k offset within chunk
    const int ks = (tid & 1) * 8;               // half2 col offset
    const float* Ap = A + (size_t)(m0 + ar) * lda + kb;

    const float* Bp;
    int nn = 0, kb2 = 0, bok = 1;
    if (NTB) {
        Bp = B + (size_t)(n0 + ar) * ldb + kb;
        bok = (n0 + ar) < N;
    } else {
        nn  = tid & 127;
        kb2 = (tid >> 7) * 16;
        Bp  = B + (size_t)kb2 * ldb + n0 + nn;
        bok = (n0 + nn) < N;
    }

    int KL = K;
    if (CMODE == 2) { int kl = m0 + 128; if (kl < KL) KL = kl; }

    float acc[4][4][4];
    #pragma unroll
    for (int i = 0; i < 4; i++)
        #pragma unroll
        for (int j = 0; j < 4; j++)
            #pragma unroll
            for (int e = 0; e < 4; e++) acc[i][j][e] = 0.f;

    float4 ra[4], rbt[4];
    float  rbn[16];

    auto loadAB = [&]() {
        #pragma unroll
        for (int j = 0; j < 4; j++) ra[j] = *(const float4*)(Ap + 4 * j);
        if (NTB) {
            if (bok) {
                #pragma unroll
                for (int j = 0; j < 4; j++) rbt[j] = *(const float4*)(Bp + 4 * j);
            } else {
                #pragma unroll
                for (int j = 0; j < 4; j++) rbt[j] = make_float4(0.f, 0.f, 0.f, 0.f);
            }
        } else {
            #pragma unroll
            for (int j = 0; j < 16; j++)
                rbn[j] = bok ? Bp[(size_t)j * ldb] : 0.f;
        }
    };
    auto storeAB = [&]() {
        uint32_t h[8];
        #pragma unroll
        for (int j = 0; j < 4; j++) {
            h[2*j]   = f2h2(ra[j].x, ra[j].y);
            h[2*j+1] = f2h2(ra[j].z, ra[j].w);
        }
        uint32_t aoff = aBase + (uint32_t)(ar * 20 + ks) * 4;
        sts128(aoff,      h[0], h[1], h[2], h[3]);
        sts128(aoff + 16, h[4], h[5], h[6], h[7]);
        if (NTB) {
            #pragma unroll
            for (int j = 0; j < 4; j++) {
                h[2*j]   = f2h2(rbt[j].x, rbt[j].y);
                h[2*j+1] = f2h2(rbt[j].z, rbt[j].w);
            }
            uint32_t boff = bBase + (uint32_t)(ar * 20 + ks) * 4;
            sts128(boff,      h[0], h[1], h[2], h[3]);
            sts128(boff + 16, h[4], h[5], h[6], h[7]);
        } else {
            #pragma unroll
            for (int j = 0; j < 8; j++) h[j] = f2h2(rbn[2*j], rbn[2*j+1]);
            uint32_t boff = bBase + (uint32_t)(nn * 20 + (kb2 >> 1)) * 4;
            sts128(boff,      h[0], h[1], h[2], h[3]);
            sts128(boff + 16, h[4], h[5], h[6], h[7]);
        }
    };

    // prologue: chunk kk=0
    loadAB();
    storeAB();
    __syncthreads();

    for (int kk = 32;; kk += 32) {
        const bool more = kk < KL;
        if (more) {
            Ap += 32;
            if (NTB) Bp += 32;
            else     Bp += (size_t)32 * ldb;
            loadAB();
        }

        #pragma unroll
        for (int s = 0; s < 2; s++) {
            const int q0 = s * 8;
            uint32_t af[4][4], bf[4][2];
            #pragma unroll
            for (int mi = 0; mi < 4; mi++) {
                int base = (wm * 64 + mi * 16 + g) * 20 + q0 + q;
                af[mi][0] = As[base];
                af[mi][1] = As[base + 160];
                af[mi][2] = As[base + 4];
                af[mi][3] = As[base + 164];
            }
            #pragma unroll
            for (int ni = 0; ni < 4; ni++) {
                int base = (wn * 32 + ni * 8 + g) * 20 + q0 + q;
                bf[ni][0] = Bs[base];
                bf[ni][1] = Bs[base + 4];
            }
            #pragma unroll
            for (int mi = 0; mi < 4; mi++)
                #pragma unroll
                for (int ni = 0; ni < 4; ni++)
                    mma_f16(acc[mi][ni], af[mi][0], af[mi][1], af[mi][2], af[mi][3],
                            bf[ni][0], bf[ni][1]);
        }

        if (!more) break;
        __syncthreads();
        storeAB();
        __syncthreads();
    }

    // -------- epilogue --------
    #pragma unroll
    for (int mi = 0; mi < 4; mi++) {
        int r0 = m0 + wm * 64 + mi * 16 + g;
        #pragma unroll
        for (int ni = 0; ni < 4; ni++) {
            int c0 = n0 + wn * 32 + ni * 8 + (q << 1);
            if (c0 >= N) continue;
            float b0 = 0.f, b1 = 0.f;
            if (bias) { b0 = bias[c0]; b1 = bias[c0 + 1]; }
            float v0 = acc[mi][ni][0] + b0, v1 = acc[mi][ni][1] + b1;
            float v2 = acc[mi][ni][2] + b0, v3 = acc[mi][ni][3] + b1;
            size_t o0 = (size_t)r0 * ldc + c0;
            size_t o1 = (size_t)(r0 + 8) * ldc + c0;
            if (resp) {
                float2 x0 = *(const float2*)(resp + o0); v0 += x0.x; v1 += x0.y;
                float2 x1 = *(const float2*)(resp + o1); v2 += x1.x; v3 += x1.y;
            }
            if (relu) {
                v0 = fmaxf(v0, 0.f); v1 = fmaxf(v1, 0.f);
                v2 = fmaxf(v2, 0.f); v3 = fmaxf(v3, 0.f);
            }
            float2 s0; s0.x = v0; s0.y = v1;
            float2 s1; s1.x = v2; s1.y = v3;
            *(float2*)(C + o0) = s0;
            *(float2*)(C + o1) = s1;
        }
    }
}

// ---------------- embedding -------------------------------------------------
__global__ void embed_kernel(const int* __restrict__ ids,
                             const float* __restrict__ te,
                             const float* __restrict__ pe,
                             float* __restrict__ x)
{
    size_t i = (size_t)blockIdx.x * blockDim.x + threadIdx.x;
    if (i >= (size_t)CB*CT*CD) return;
    int d = (int)(i % CD);
    size_t bt = i / CD;
    int t = (int)(bt % CT);
    x[i] = te[(size_t)ids[bt]*CD + d] + pe[(size_t)t*CD + d];
}

// ---------------- layernorm --------------------------------------------------
__global__ void layernorm_kernel(const float* __restrict__ x, float* __restrict__ y,
                                 const float* __restrict__ g, const float* __restrict__ bb)
{
    int row = blockIdx.x;
    const float* xr = x + (size_t)row * CD;
    float* yr = y + (size_t)row * CD;
    float s = 0.f, s2 = 0.f;
    for (int i = threadIdx.x; i < CD; i += blockDim.x) {
        float u = xr[i]; s += u; s2 += u*u;
    }
    __shared__ float rs[32], rs2[32], stats[2];
    #pragma unroll
    for (int o = 16; o; o >>= 1) {
        s  += __shfl_xor_sync(0xffffffffu, s,  o);
        s2 += __shfl_xor_sync(0xffffffffu, s2, o);
    }
    int wid = threadIdx.x >> 5;
    if ((threadIdx.x & 31) == 0) { rs[wid] = s; rs2[wid] = s2; }
    __syncthreads();
    if (threadIdx.x == 0) {
        float ts = 0.f, ts2 = 0.f;
        int nw = blockDim.x >> 5;
        for (int i = 0; i < nw; i++) { ts += rs[i]; ts2 += rs2[i]; }
        float m = ts / (float)CD;
        float var = ts2 / (float)CD - m*m;
        stats[0] = m; stats[1] = rsqrtf(var + 1e-5f);
    }
    __syncthreads();
    float m = stats[0], r = stats[1];
    for (int i = threadIdx.x; i < CD; i += blockDim.x)
        yr[i] = (xr[i] - m) * r * g[i] + bb[i];
}

// ---- fused wq/wk/wv transpose: 3 x (H,D,HS) -> (D, 3*H*HS) ld=3072 ----------
__global__ void transpose_w3(const float* __restrict__ wq,
                             const float* __restrict__ wk,
                             const float* __restrict__ wv,
                             float* __restrict__ dst)
{
    int fid = blockIdx.x * blockDim.x + threadIdx.x;  // float4 index
    const int per = (CD * CD) >> 2;                    // 262144
    if (fid >= 3 * per) return;
    int w = fid / per, r = fid - w * per;
    int d = r >> 8, rem = r & 255, hh = rem >> 4, e4 = (rem & 15) << 2;
    const float* src = (w == 0) ? wq : ((w == 1) ? wk : wv);
    float4 v = *(const float4*)(src + ((size_t)hh * CD + d) * CHS + e4);
    *(float4*)(dst + (size_t)d * CQKV + w * CD + hh * CHS + e4) = v;
}

// ---------------- causal softmax; zeros only to next 128 boundary ------------
__global__ void softmax_causal(float* __restrict__ S)
{
    int row = blockIdx.x;          // (b*H+h)*T + t
    int t = row & (CT - 1);
    float* p = S + (size_t)row * CT;
    int n = t + 1;
    const float scale = 0.03125f;  // 1024^-0.5

    __shared__ float red[32];
    __shared__ float bval;

    float m = -1e30f;
    for (int j = threadIdx.x; j < n; j += blockDim.x) m = fmaxf(m, p[j] * scale);
    #pragma unroll
    for (int o = 16; o; o >>= 1) m = fmaxf(m, __shfl_xor_sync(0xffffffffu, m, o));
    int wid = threadIdx.x >> 5;
    if ((threadIdx.x & 31) == 0) red[wid] = m;
    __syncthreads();
    if (threadIdx.x == 0) {
        float mm = -1e30f; int nw = blockDim.x >> 5;
        for (int i = 0; i < nw; i++) mm = fmaxf(mm, red[i]);
        bval = mm;
    }
    __syncthreads();
    float bmax = bval;

    float s = 0.f;
    for (int j = threadIdx.x; j < n; j += blockDim.x) {
        float e = __expf(p[j] * scale - bmax);
        p[j] = e; s += e;
    }
    __syncthreads();
    #pragma unroll
    for (int o = 16; o; o >>= 1) s += __shfl_xor_sync(0xffffffffu, s, o);
    if ((threadIdx.x & 31) == 0) red[wid] = s;
    __syncthreads();
    if (threadIdx.x == 0) {
        float ss = 0.f; int nw = blockDim.x >> 5;
        for (int i = 0; i < nw; i++) ss += red[i];
        bval = ss;
    }
    __syncthreads();
    float inv = 1.f / bval;
    for (int j = threadIdx.x; j < n; j += blockDim.x) p[j] *= inv;
    int zend = ((t >> 7) + 1) << 7;    // AV reads k < m0+128 only
    for (int j = n + threadIdx.x; j < zend; j += blockDim.x) p[j] = 0.f;
}

// ---------------- host orchestration ----------------------------------------
extern "C" void kernel_launch(void* const* d_in, const int* in_sizes, int n_in,
                              void* d_out, int out_size)
{
    (void)in_sizes; (void)n_in; (void)out_size;
    const int*   ids  = (const int*)  d_in[0];
    const float* tok  = (const float*)d_in[1];
    const float* pos  = (const float*)d_in[2];
    const float* wq   = (const float*)d_in[3];
    const float* wk   = (const float*)d_in[4];
    const float* wv   = (const float*)d_in[5];
    const float* wprj = (const float*)d_in[6];
    const float* bprj = (const float*)d_in[7];
    const float* ln1g = (const float*)d_in[8];
    const float* ln1b = (const float*)d_in[9];
    const float* ln2g = (const float*)d_in[10];
    const float* ln2b = (const float*)d_in[11];
    const float* w1   = (const float*)d_in[12];
    const float* b1   = (const float*)d_in[13];
    const float* w2   = (const float*)d_in[14];
    const float* b2   = (const float*)d_in[15];
    const float* lnfg = (const float*)d_in[16];
    const float* lnfb = (const float*)d_in[17];
    const float* wout = (const float*)d_in[18];
    const float* bout = (const float*)d_in[19];
    float* out = (float*)d_out;

    float *x, *h, *qkv, *o, *ffn, *s, *wt;
    cudaGetSymbolAddress((void**)&x,   g_x);
    cudaGetSymbolAddress((void**)&h,   g_h);
    cudaGetSymbolAddress((void**)&qkv, g_qkv);
    cudaGetSymbolAddress((void**)&o,   g_o);
    cudaGetSymbolAddress((void**)&ffn, g_ffn);
    cudaGetSymbolAddress((void**)&s,   g_s);
    cudaGetSymbolAddress((void**)&wt,  g_wt);

    const int NT = CB * CT;                       // 4096 rows
    const long long TQ = (long long)CT * CQKV;    // qkv batch stride (per b)
    const long long TD = (long long)CT * CD;
    const long long TT = (long long)CT * CT;

    // 1. embedding
    {
        size_t tot = (size_t)CB * CT * CD;
        embed_kernel<<<(unsigned)((tot + 255) / 256), 256>>>(ids, tok, pos, x);
    }

    for (int l = 0; l < CL; l++) {
        const size_t wOff = (size_t)l * CD * CD;

        // 2. ln1
        layernorm_kernel<<<NT, 256>>>(x, h, ln1g + (size_t)l*CD, ln1b + (size_t)l*CD);

        // 3. fused qkv weight transpose -> (D, 3072)
        {
            int tot4 = 3 * (CD * CD) / 4;
            transpose_w3<<<(tot4 + 255) / 256, 256>>>(wq + wOff, wk + wOff, wv + wOff, wt);
        }

        // 4. fused QKV projection: (4096 x 1024) @ (1024 x 3072)
        {
            dim3 grid(NT / 128, CQKV / 128, 1);
            hgemm<0,0><<<grid, 256>>>(h, CD, 0, 0, wt, CQKV, 0, 0,
                                      qkv, CQKV, 0, 0,
                                      1, CQKV, CD, nullptr, nullptr, 0);
        }

        // 5. scores S = Q @ K^T per (b,h), causal tile-skip
        {
            dim3 grid(CT / 128, CT / 128, CB * CH);
            hgemm<1,1><<<grid, 256>>>(qkv,      CQKV, TQ, CHS,
                                      qkv + CD, CQKV, TQ, CHS,
                                      s, CT, (long long)CH * TT, TT,
                                      CH, CT, CHS, nullptr, nullptr, 0);
        }

        // 6. causal softmax
        softmax_causal<<<CB * CH * CT, 128>>>(s);

        // 7. O = P @ V per (b,h), causal K-limit (N=64, guarded)
        {
            dim3 grid(CT / 128, 1, CB * CH);
            hgemm<0,2><<<grid, 256>>>(s, CT, (long long)CH * TT, TT,
                                      qkv + 2 * CD, CQKV, TQ, CHS,
                                      o, CD, TD, CHS,
                                      CH, CHS, CT, nullptr, nullptr, 0);
        }

        // 8. out projection + bias + residual
        {
            dim3 grid(NT / 128, CD / 128, 1);
            hgemm<0,0><<<grid, 256>>>(o, CD, 0, 0, wprj + (size_t)l*CD*CD, CD, 0, 0,
                                      x, CD, 0, 0, 1, CD, CD,
                                      bprj + (size_t)l*CD, x, 0);
        }

        // 9. ln2
        layernorm_kernel<<<NT, 256>>>(x, h, ln2g + (size_t)l*CD, ln2b + (size_t)l*CD);

        // 10. FFN up + relu
        {
            dim3 grid(NT / 128, CFF / 128, 1);
            hgemm<0,0><<<grid, 256>>>(h, CD, 0, 0, w1 + (size_t)l*CD*CFF, CFF, 0, 0,
                                      ffn, CFF, 0, 0, 1, CFF, CD,
                                      b1 + (size_t)l*CFF, nullptr, 1);
        }

        // 11. FFN down + bias + residual
        {
            dim3 grid(NT / 128, CD / 128, 1);
            hgemm<0,0><<<grid, 256>>>(ffn, CFF, 0, 0, w2 + (size_t)l*CFF*CD, CD, 0, 0,
                                      x, CD, 0, 0, 1, CD, CFF,
                                      b2 + (size_t)l*CD, x, 0);
        }
    }

    // 12. final layernorm
    layernorm_kernel<<<NT, 256>>>(x, h, lnfg, lnfb);

    // 13. logits: (4096 x 1024) @ (1024 x 32000) + b_out
    {
        dim3 grid(NT / 128, CV / 128, 1);
        hgemm<0,0><<<grid, 256>>>(h, CD, 0, 0, wout, CV, 0, 0,
                                  out, CV, 0, 0, 1, CV, CD,
                                  bout, nullptr, 0);
    }
}